// round 16
// baseline (speedup 1.0000x reference)
#include <cuda_runtime.h>
#include <cuda_bf16.h>
#include <cstdint>

// NeRF volume rendering compositing, GB300 (sm_103a). FINAL.
// rgb: [B, 64, 3] f32, sigma: [B, 64] f32
// out: [B*3] rgb_map ++ [B] depth_map (f32)
//
// Champion configuration (best of 12 measured variants):
//   - 2 rays per warp, 16 lanes per ray, 4 samples per lane.
//   - No smem, no block barriers: warps fully autonomous, so load and
//     compute phases of different warps overlap freely (smem staging with
//     __syncthreads measured -20% DRAM bw).
//   - 4 front-batched streaming LDG.128 per thread (1 sigma + 3 rgb), all
//     __ldcs: read-once 272MB stream, evict-first. (8-load / 54-reg variants
//     measured worse: occupancy cliff at >32 regs outweighs extra MLP.)
//   - Width-16 segmented shuffle product-scan (exact exclusive cumprod, no
//     division) + width-16 butterfly reduction shared by the 2 rays.
//     (redux.sync.add.f32 is NOT in the sm_103a ISA - verified by ptxas.)
//   - Plain stores (__stcs on scattered STG.32 measured -3% DRAM bw).
// Measured: 40.7-41.7us kernel, 83-85% DRAM (6.6-6.7 TB/s), traffic minimal.

#define NERF_S 64

__global__ __launch_bounds__(256) void nerf_render_kernel(
    const float4* __restrict__ rgb4,   // [B*48] float4
    const float4* __restrict__ sig4,   // [B*16] float4
    float* __restrict__ out,
    int n_rays)
{
    const int warp_g = (blockIdx.x * blockDim.x + threadIdx.x) >> 5;
    const int lane   = threadIdx.x & 31;
    const int half   = lane >> 4;          // 0 = ray A, 1 = ray B
    const int j      = lane & 15;          // segment position (0..15)
    const int ray    = warp_g * 2 + half;
    if (ray >= n_rays) return;

    // ---- front-batched streaming loads (fully coalesced LDG.128) ----
    // sigma: warp covers 512B = both rays; lane l -> ray (l>>4), samples 4j..4j+3
    const float4 sg = __ldcs(sig4 + (size_t)warp_g * 32 + lane);

    // rgb: lane needs 12 floats at ray*192 + 12*j  (three float4, 16B aligned)
    const float4* rp = rgb4 + ((size_t)ray * 192 + 12 * j) / 4;
    float4 c0 = __ldcs(rp + 0);
    float4 c1 = __ldcs(rp + 1);
    float4 c2 = __ldcs(rp + 2);

    // ---- per-sample transmittance factors ----
    float e0 = __expf(-sg.x);
    float e1 = __expf(-sg.y);
    float e2 = __expf(-sg.z);
    float e3 = __expf(-sg.w);

    float t0 = e0 + 1e-10f;
    float t1 = e1 + 1e-10f;
    float t2 = e2 + 1e-10f;
    float t3 = e3 + 1e-10f;

    // local exclusive products
    float l1 = t0;
    float l2 = t0 * t1;
    float l3 = l2 * t2;
    float p  = l3 * t3;               // local total product

    // ---- width-16 inclusive product scan (4 steps) ----
    float incl = p;
    #pragma unroll
    for (int off = 1; off < 16; off <<= 1) {
        float v = __shfl_up_sync(0xffffffffu, incl, off, 16);
        if (j >= off) incl *= v;
    }
    float E = __shfl_up_sync(0xffffffffu, incl, 1, 16);  // exclusive
    if (j == 0) E = 1.0f;

    // weights
    float w0 = (1.0f - e0) * E;
    float w1 = (1.0f - e1) * (E * l1);
    float w2 = (1.0f - e2) * (E * l2);
    float w3 = (1.0f - e3) * (E * l3);

    // ---- weighted sums ----
    float r = w0 * c0.x + w1 * c0.w + w2 * c1.z + w3 * c2.y;
    float g = w0 * c0.y + w1 * c1.x + w2 * c1.w + w3 * c2.z;
    float b = w0 * c0.z + w1 * c1.y + w2 * c2.x + w3 * c2.w;

    const float step = 4.0f / 63.0f;      // linspace(2, 6, 64)
    const float tv = 2.0f + step * (float)(4 * j);
    float d = w0 * tv
            + w1 * (tv + step)
            + w2 * (tv + 2.0f * step)
            + w3 * (tv + 3.0f * step);

    // ---- width-16 butterfly reduction (shared by the 2 rays) ----
    #pragma unroll
    for (int off = 8; off > 0; off >>= 1) {
        r += __shfl_xor_sync(0xffffffffu, r, off, 16);
        g += __shfl_xor_sync(0xffffffffu, g, off, 16);
        b += __shfl_xor_sync(0xffffffffu, b, off, 16);
        d += __shfl_xor_sync(0xffffffffu, d, off, 16);
    }

    if (j == 0) {
        out[(size_t)ray * 3 + 0] = r;
        out[(size_t)ray * 3 + 1] = g;
        out[(size_t)ray * 3 + 2] = b;
        out[(size_t)n_rays * 3 + ray] = d;
    }
}

extern "C" void kernel_launch(void* const* d_in, const int* in_sizes, int n_in,
                              void* d_out, int out_size)
{
    const float4* rgb4 = (const float4*)d_in[0];   // [B, 64, 3]
    const float4* sig4 = (const float4*)d_in[1];   // [B, 64]
    float* out = (float*)d_out;

    const int n_rays = in_sizes[1] / NERF_S;

    // 256 threads = 8 warps = 16 rays per block
    const int rays_per_block = 16;
    const int blocks = (n_rays + rays_per_block - 1) / rays_per_block;
    nerf_render_kernel<<<blocks, 256>>>(rgb4, sig4, out, n_rays);
}

// round 17
// speedup vs baseline: 1.0564x; 1.0564x over previous
#include <cuda_runtime.h>
#include <cuda_bf16.h>
#include <cstdint>

// NeRF volume rendering compositing, GB300 (sm_103a). FINAL family.
// rgb: [B, 64, 3] f32, sigma: [B, 64] f32
// out: [B*3] rgb_map ++ [B] depth_map (f32)
//
// Champion configuration (best of 13 measured variants):
//   - 2 rays per warp, 16 lanes per ray, 4 samples per lane.
//   - No smem, no block barriers: warps fully autonomous (smem staging
//     with __syncthreads measured -20% DRAM bw).
//   - 4 front-batched LDG.128 per thread (1 sigma + 3 rgb). This round:
//     __ldlu (last-use) instead of __ldcs — inputs are read-once, so the
//     line can be dropped from L2 immediately after the read.
//   - Width-16 segmented shuffle product-scan (exact exclusive cumprod)
//     + width-16 butterfly reduction shared by the 2 rays.
//   - Plain stores (__stcs measured -3% DRAM bw).

#define NERF_S 64

__global__ __launch_bounds__(256) void nerf_render_kernel(
    const float4* __restrict__ rgb4,   // [B*48] float4
    const float4* __restrict__ sig4,   // [B*16] float4
    float* __restrict__ out,
    int n_rays)
{
    const int warp_g = (blockIdx.x * blockDim.x + threadIdx.x) >> 5;
    const int lane   = threadIdx.x & 31;
    const int half   = lane >> 4;          // 0 = ray A, 1 = ray B
    const int j      = lane & 15;          // segment position (0..15)
    const int ray    = warp_g * 2 + half;
    if (ray >= n_rays) return;

    // ---- front-batched last-use loads (fully coalesced LDG.128) ----
    // sigma: warp covers 512B = both rays; lane l -> ray (l>>4), samples 4j..4j+3
    const float4 sg = __ldlu(sig4 + (size_t)warp_g * 32 + lane);

    // rgb: lane needs 12 floats at ray*192 + 12*j  (three float4, 16B aligned)
    const float4* rp = rgb4 + ((size_t)ray * 192 + 12 * j) / 4;
    float4 c0 = __ldlu(rp + 0);
    float4 c1 = __ldlu(rp + 1);
    float4 c2 = __ldlu(rp + 2);

    // ---- per-sample transmittance factors ----
    float e0 = __expf(-sg.x);
    float e1 = __expf(-sg.y);
    float e2 = __expf(-sg.z);
    float e3 = __expf(-sg.w);

    float t0 = e0 + 1e-10f;
    float t1 = e1 + 1e-10f;
    float t2 = e2 + 1e-10f;
    float t3 = e3 + 1e-10f;

    // local exclusive products
    float l1 = t0;
    float l2 = t0 * t1;
    float l3 = l2 * t2;
    float p  = l3 * t3;               // local total product

    // ---- width-16 inclusive product scan (4 steps) ----
    float incl = p;
    #pragma unroll
    for (int off = 1; off < 16; off <<= 1) {
        float v = __shfl_up_sync(0xffffffffu, incl, off, 16);
        if (j >= off) incl *= v;
    }
    float E = __shfl_up_sync(0xffffffffu, incl, 1, 16);  // exclusive
    if (j == 0) E = 1.0f;

    // weights
    float w0 = (1.0f - e0) * E;
    float w1 = (1.0f - e1) * (E * l1);
    float w2 = (1.0f - e2) * (E * l2);
    float w3 = (1.0f - e3) * (E * l3);

    // ---- weighted sums ----
    float r = w0 * c0.x + w1 * c0.w + w2 * c1.z + w3 * c2.y;
    float g = w0 * c0.y + w1 * c1.x + w2 * c1.w + w3 * c2.z;
    float b = w0 * c0.z + w1 * c1.y + w2 * c2.x + w3 * c2.w;

    const float step = 4.0f / 63.0f;      // linspace(2, 6, 64)
    const float tv = 2.0f + step * (float)(4 * j);
    float d = w0 * tv
            + w1 * (tv + step)
            + w2 * (tv + 2.0f * step)
            + w3 * (tv + 3.0f * step);

    // ---- width-16 butterfly reduction (shared by the 2 rays) ----
    #pragma unroll
    for (int off = 8; off > 0; off >>= 1) {
        r += __shfl_xor_sync(0xffffffffu, r, off, 16);
        g += __shfl_xor_sync(0xffffffffu, g, off, 16);
        b += __shfl_xor_sync(0xffffffffu, b, off, 16);
        d += __shfl_xor_sync(0xffffffffu, d, off, 16);
    }

    if (j == 0) {
        out[(size_t)ray * 3 + 0] = r;
        out[(size_t)ray * 3 + 1] = g;
        out[(size_t)ray * 3 + 2] = b;
        out[(size_t)n_rays * 3 + ray] = d;
    }
}

extern "C" void kernel_launch(void* const* d_in, const int* in_sizes, int n_in,
                              void* d_out, int out_size)
{
    const float4* rgb4 = (const float4*)d_in[0];   // [B, 64, 3]
    const float4* sig4 = (const float4*)d_in[1];   // [B, 64]
    float* out = (float*)d_out;

    const int n_rays = in_sizes[1] / NERF_S;

    // 256 threads = 8 warps = 16 rays per block
    const int rays_per_block = 16;
    const int blocks = (n_rays + rays_per_block - 1) / rays_per_block;
    nerf_render_kernel<<<blocks, 256>>>(rgb4, sig4, out, n_rays);
}